// round 9
// baseline (speedup 1.0000x reference)
#include <cuda_runtime.h>
#include <cuda_bf16.h>
#include <cstdint>

// Problem constants
#define B_  8
#define C_  128
#define H_  256
#define W_  256
#define KB_ 4
#define OC_ 128

// Scratch (static device arrays; no allocation)
__device__ float g_pooled[B_ * C_];
__device__ float g_dynk[B_ * C_ * 9];
// pw_w split to bf16 hi + bf16 residual lo, packed in m16n8k16 B-fragment
// order: [ci(8)][nt(16)][lane(32)][4 words: bh0, bh1, bl0, bl1]
__device__ uint32_t g_pwf[8 * 16 * 32 * 4];        // 16384 u32

// ---------------------------------------------------------------------------
// helpers
// ---------------------------------------------------------------------------
__device__ __forceinline__ uint32_t smem_u32(const void* p) {
    uint32_t a;
    asm("{ .reg .u64 t; cvta.to.shared.u64 t, %1; cvt.u32.u64 %0, t; }"
        : "=r"(a) : "l"(p));
    return a;
}
__device__ __forceinline__ void mma_bf16(float* d, const uint32_t* a,
                                         uint32_t b0, uint32_t b1) {
    asm volatile(
        "mma.sync.aligned.m16n8k16.row.col.f32.bf16.bf16.f32 "
        "{%0,%1,%2,%3}, {%4,%5,%6,%7}, {%8,%9}, {%0,%1,%2,%3};"
        : "+f"(d[0]), "+f"(d[1]), "+f"(d[2]), "+f"(d[3])
        : "r"(a[0]), "r"(a[1]), "r"(a[2]), "r"(a[3]), "r"(b0), "r"(b1));
}
// split float into bf16 hi bits + bf16 residual bits
__device__ __forceinline__ uint32_t split_bf16_pair(float v) {
    __nv_bfloat16 h = __float2bfloat16_rn(v);
    float hif = __bfloat162float(h);
    __nv_bfloat16 l = __float2bfloat16_rn(v - hif);
    return (uint32_t)__bfloat16_as_ushort(h)
         | ((uint32_t)__bfloat16_as_ushort(l) << 16);
}

// ---------------------------------------------------------------------------
// Kernel 1: global average pool
// ---------------------------------------------------------------------------
__global__ void pool_kernel(const float* __restrict__ x) {
    const int plane = blockIdx.x;
    const int t = threadIdx.x;
    const float4* p = reinterpret_cast<const float4*>(x + (size_t)plane * (H_ * W_));
    float s = 0.f;
#pragma unroll 8
    for (int it = 0; it < 64; it++) {
        float4 v = p[it * 256 + t];
        s += (v.x + v.y) + (v.z + v.w);
    }
    __shared__ float red[256];
    red[t] = s;
    __syncthreads();
    for (int st = 128; st > 0; st >>= 1) {
        if (t < st) red[t] += red[t + st];
        __syncthreads();
    }
    if (t == 0) g_pooled[plane] = red[0] * (1.f / (H_ * W_));
}

// ---------------------------------------------------------------------------
// Kernel 2: attention -> softmax -> dynamic depthwise kernel per (b,c)
// ---------------------------------------------------------------------------
__global__ void attn_kernel(const float* __restrict__ kernel_bank,
                            const float* __restrict__ attn_w,
                            const float* __restrict__ attn_b) {
    const int b = blockIdx.x;
    const int c = threadIdx.x;               // 128 threads
    __shared__ float red[128];
    __shared__ float logit[KB_];
    __shared__ float attn[KB_];

    float p = g_pooled[b * C_ + c];
    for (int k = 0; k < KB_; k++) {
        red[c] = p * attn_w[k * C_ + c];
        __syncthreads();
        for (int st = 64; st > 0; st >>= 1) {
            if (c < st) red[c] += red[c + st];
            __syncthreads();
        }
        if (c == 0) logit[k] = red[0] + attn_b[k];
        __syncthreads();
    }
    if (c == 0) {
        float mx = logit[0];
        for (int k = 1; k < KB_; k++) mx = fmaxf(mx, logit[k]);
        float s = 0.f;
        for (int k = 0; k < KB_; k++) { attn[k] = expf(logit[k] - mx); s += attn[k]; }
        float inv = 1.f / s;
        for (int k = 0; k < KB_; k++) attn[k] *= inv;
    }
    __syncthreads();
    float a0 = attn[0], a1 = attn[1], a2 = attn[2], a3 = attn[3];
#pragma unroll
    for (int ij = 0; ij < 9; ij++) {
        float s = a0 * kernel_bank[(0 * C_ + c) * 9 + ij]
                + a1 * kernel_bank[(1 * C_ + c) * 9 + ij]
                + a2 * kernel_bank[(2 * C_ + c) * 9 + ij]
                + a3 * kernel_bank[(3 * C_ + c) * 9 + ij];
        g_dynk[(b * C_ + c) * 9 + ij] = s;
    }
}

// ---------------------------------------------------------------------------
// Kernel 2b: split pw_w to bf16 hi/lo, packed in B-fragment order.
// ---------------------------------------------------------------------------
__global__ void split_pw_frag(const float* __restrict__ pw_w) {
    int idx = blockIdx.x * 256 + threadIdx.x;   // (ci, nt, lane)
    if (idx >= 4096) return;
    int lane = idx & 31;
    int nt   = (idx >> 5) & 15;
    int ci   = idx >> 9;
    int g = lane >> 2, tig = lane & 3;
    int o  = nt * 8 + g;
    int k0 = ci * 16 + 2 * tig;

    uint32_t p00 = split_bf16_pair(pw_w[o * C_ + k0]);       // {hi,lo}
    uint32_t p01 = split_bf16_pair(pw_w[o * C_ + k0 + 1]);
    uint32_t p10 = split_bf16_pair(pw_w[o * C_ + k0 + 8]);
    uint32_t p11 = split_bf16_pair(pw_w[o * C_ + k0 + 9]);

    g_pwf[idx * 4 + 0] = __byte_perm(p00, p01, 0x5410);      // bh0
    g_pwf[idx * 4 + 1] = __byte_perm(p10, p11, 0x5410);      // bh1
    g_pwf[idx * 4 + 2] = __byte_perm(p00, p01, 0x7632);      // bl0
    g_pwf[idx * 4 + 3] = __byte_perm(p10, p11, 0x7632);      // bl1
}

// ---------------------------------------------------------------------------
// Fused dw 3x3 + mma.sync bf16 GEMM, M=256 tile (2 output rows per CTA).
// Grid (2, 128, 8), 512 threads, 1 CTA/SM.
// dw spread over ALL 16 warps: thread (kch = t&15, mg = t>>4, mg 0..31),
//   8 pixels x 1 output row each (rows balanced across warps).
// B fragments read directly from global via __ldg (4x L1 reuse per wn-quad);
// no Bs smem ring.
// Smem (floats):
//   As[2]  : buf stride 4128 (hi 2048 @+0, lo 2048 @+2064)
//   xs[2]  : 16ch x 4rows x 140, ch stride 564 (141 16B-units, odd -> CF)
//   dk     : 1152
// ---------------------------------------------------------------------------
#define XS_ROWST 140
#define XS_CH    564
#define XS_FLTS  (16 * XS_CH)               // 9024 per buffer
#define AS_F     0
#define AS_LO_D  2064
#define AS_STRIDE 4128
#define XS_F     8256
#define DK_F     (XS_F + 2 * XS_FLTS)       // 26304
#define SMEM_FLOATS (DK_F + 1152)           // 27456 -> 109824 B

__device__ __forceinline__ void stage_xs(const float* __restrict__ x,
                                         int b, int c0, int h0, int w0,
                                         float* xf, int t) {
    // interior: 16 ch x 4 rows x 32 float4 = 2048 f4, 4 per thread
#pragma unroll
    for (int i = 0; i < 4; i++) {
        int idx = t + i * 512;
        int c   = idx >> 7;
        int rem = idx & 127;
        int r   = rem >> 5;
        int q   = rem & 31;
        int hh  = h0 + r - 1;
        float* dst = xf + c * XS_CH + r * XS_ROWST + 4 + q * 4;
        if ((unsigned)hh < (unsigned)H_) {
            const float* src = x + (((size_t)(b * C_ + c0 + c)) * H_ + hh) * W_ + w0 + q * 4;
            asm volatile("cp.async.cg.shared.global [%0], [%1], 16;"
                         :: "r"(smem_u32(dst)), "l"(src));
        } else {
            *reinterpret_cast<float4*>(dst) = make_float4(0.f, 0.f, 0.f, 0.f);
        }
    }
    // halo columns: 16 ch x 4 rows x 2 sides = 128 scalars
    if (t < 128) {
        int c    = t >> 3;
        int rem  = t & 7;
        int r    = rem >> 1;
        int side = rem & 1;
        int hh   = h0 + r - 1;
        int ww   = side ? (w0 + 128) : (w0 - 1);
        int col  = side ? 132 : 3;
        float* dst = xf + c * XS_CH + r * XS_ROWST + col;
        if ((unsigned)hh < (unsigned)H_ && (unsigned)ww < (unsigned)W_) {
            const float* src = x + (((size_t)(b * C_ + c0 + c)) * H_ + hh) * W_ + ww;
            asm volatile("cp.async.ca.shared.global [%0], [%1], 4;"
                         :: "r"(smem_u32(dst)), "l"(src));
        } else {
            *dst = 0.f;
        }
    }
}

// depthwise for chunk cj: 8 pixels, ONE output row per thread
__device__ __forceinline__ void dw_chunk(float* smem, int cj, int kch, int mg,
                                         int wb, int a_lo_sel, uint32_t psel) {
    const float* dk  = smem + DK_F;
    const float* dkc = dk + (cj * 16 + kch) * 9;
    const int row    = mg >> 4;              // output row 0 or 1
    const int px     = (mg & 15) * 8;        // pixel base within row
    const float* rowb = smem + XS_F + (cj & 1) * XS_FLTS + kch * XS_CH
                      + row * XS_ROWST + px;
    float sv[8];
#pragma unroll
    for (int j = 0; j < 8; j++) sv[j] = 0.f;
#pragma unroll
    for (int r = 0; r < 3; r++) {
        const float* rp = rowb + r * XS_ROWST;
        float4 q0 = *reinterpret_cast<const float4*>(rp);
        float4 q1 = *reinterpret_cast<const float4*>(rp + 4);
        float4 q2 = *reinterpret_cast<const float4*>(rp + 8);
        float4 q3 = *reinterpret_cast<const float4*>(rp + 12);
        float v[16] = {q0.x, q0.y, q0.z, q0.w, q1.x, q1.y, q1.z, q1.w,
                       q2.x, q2.y, q2.z, q2.w, q3.x, q3.y, q3.z, q3.w};
        float k0 = dkc[r * 3 + 0], k1 = dkc[r * 3 + 1], k2 = dkc[r * 3 + 2];
#pragma unroll
        for (int j = 0; j < 8; j++) {
            sv[j] = fmaf(k0, v[j + 3], sv[j]);
            sv[j] = fmaf(k1, v[j + 4], sv[j]);
            sv[j] = fmaf(k2, v[j + 5], sv[j]);
        }
    }
    float* abase = smem + AS_F + (cj & 1) * AS_STRIDE + a_lo_sel;
#pragma unroll
    for (int j = 0; j < 8; j++) {
        uint32_t own = split_bf16_pair(sv[j]);
        uint32_t partner = __shfl_xor_sync(0xffffffffu, own, 1);
        abase[wb + j * 16] = __uint_as_float(__byte_perm(own, partner, psel));
    }
}

__global__ __launch_bounds__(512, 1)
void fused_kernel(const float* __restrict__ x,
                  const float* __restrict__ pw_b,
                  float* __restrict__ out) {
    extern __shared__ float smem[];
    float* dk = smem + DK_F;

    const int t    = threadIdx.x;
    const int wid  = t >> 5;
    const int lane = t & 31;
    const int w0   = blockIdx.x * 128;
    const int h0   = blockIdx.y * 2;
    const int bb   = blockIdx.z;

    // dw mapping: channel kch, pixel-group mg (0..31; mg>>4 = output row)
    const int kch = t & 15;
    const int mg  = t >> 4;
    const int mt_dw = (mg >> 4) * 8 + ((mg & 15) >> 1);
    const int wb = mt_dw * 128 + ((kch >> 1) & 3) * 4
                 + (kch >> 3) * 2 + (mg & 1);
    const int a_lo_sel = (kch & 1) ? AS_LO_D : 0;
    const uint32_t psel = (kch & 1) ? 0x3276u : 0x5410u;

    // GEMM warp tiling: 4 m-warps x 4 n-warps, warp tile m64 x n32
    const int wm = wid & 3;
    const int wn = wid >> 2;
    const uint4* bsrc = reinterpret_cast<const uint4*>(g_pwf) + wn * 4 * 32 + lane;

    // prologue
    stage_xs(x, bb, 0, h0, w0, smem + XS_F, t);
    asm volatile("cp.async.commit_group;" ::: "memory");
    for (int i = t; i < C_ * 9; i += 512)
        dk[i] = g_dynk[bb * C_ * 9 + i];

    float acc[4][4][4];
#pragma unroll
    for (int i = 0; i < 4; i++)
#pragma unroll
        for (int j = 0; j < 4; j++)
#pragma unroll
            for (int k = 0; k < 4; k++) acc[i][j][k] = 0.f;

    asm volatile("cp.async.wait_group 0;" ::: "memory");
    __syncthreads();
    stage_xs(x, bb, 16, h0, w0, smem + XS_F + XS_FLTS, t);
    asm volatile("cp.async.commit_group;" ::: "memory");

    dw_chunk(smem, 0, kch, mg, wb, a_lo_sel, psel);

#pragma unroll 1
    for (int ci = 0; ci < 8; ci++) {
        if (ci < 7)
            asm volatile("cp.async.wait_group 0;" ::: "memory");
        __syncthreads();   // dw(ci) visible; GEMM(ci-1) done with As[(ci+1)&1]

        // B fragments for GEMM(ci): direct LDG, latency hidden by dw below
        uint4 bfrag[4];
#pragma unroll
        for (int ntl = 0; ntl < 4; ntl++)
            bfrag[ntl] = __ldg(bsrc + ci * 512 + ntl * 32);

        if (ci < 6) {
            stage_xs(x, bb, (ci + 2) * 16, h0, w0, smem + XS_F + (ci & 1) * XS_FLTS, t);
            asm volatile("cp.async.commit_group;" ::: "memory");
        }

        // dw(ci+1) overlaps the B LDGs and fills the fma pipe
        if (ci < 7)
            dw_chunk(smem, ci + 1, kch, mg, wb, a_lo_sel, psel);

        // --- GEMM(ci): one k16 step, 3xBF16 split, 2 m-halves ---
        {
            const float* asb = smem + AS_F + (ci & 1) * AS_STRIDE;
#pragma unroll
            for (int half = 0; half < 2; half++) {
                uint4 ah[2], al[2];
#pragma unroll
                for (int mA = 0; mA < 2; mA++) {
                    int mt = wm * 4 + half * 2 + mA;
                    int fi = (mt * 32 + lane) * 4;
                    ah[mA] = *reinterpret_cast<const uint4*>(asb + fi);
                    al[mA] = *reinterpret_cast<const uint4*>(asb + AS_LO_D + fi);
                }
#pragma unroll
                for (int ntl = 0; ntl < 4; ntl++) {
                    uint4 bv = bfrag[ntl];
#pragma unroll
                    for (int mA = 0; mA < 2; mA++) {
                        float* a4 = acc[half * 2 + mA][ntl];
                        mma_bf16(a4, reinterpret_cast<uint32_t*>(&ah[mA]), bv.x, bv.y);
                        mma_bf16(a4, reinterpret_cast<uint32_t*>(&al[mA]), bv.x, bv.y);
                        mma_bf16(a4, reinterpret_cast<uint32_t*>(&ah[mA]), bv.z, bv.w);
                    }
                }
            }
        }
    }

    // --- epilogue: D fragment scatter + bias ---
    const int g   = lane >> 2;
    const int tig = lane & 3;
#pragma unroll
    for (int mA = 0; mA < 4; mA++) {
        int mbase = wm * 64 + mA * 16;
        int h  = h0 + (mbase >> 7);          // mbase..mbase+15 in same row
        int wp = w0 + (mbase & 127);
#pragma unroll
        for (int ntl = 0; ntl < 4; ntl++) {
            int o = wn * 32 + ntl * 8 + 2 * tig;
            float b0v = __ldg(pw_b + o);
            float b1v = __ldg(pw_b + o + 1);
            size_t r0 = (((size_t)(bb * OC_ + o)) * H_ + h) * W_ + wp;
            size_t r1 = r0 + (size_t)H_ * W_;
            const float* a4 = acc[mA][ntl];
            out[r0 + g]     = a4[0] + b0v;
            out[r1 + g]     = a4[1] + b1v;
            out[r0 + g + 8] = a4[2] + b0v;
            out[r1 + g + 8] = a4[3] + b1v;
        }
    }
}

// ---------------------------------------------------------------------------
extern "C" void kernel_launch(void* const* d_in, const int* in_sizes, int n_in,
                              void* d_out, int out_size) {
    const float* x           = (const float*)d_in[0];
    const float* kernel_bank = (const float*)d_in[1];
    const float* attn_w      = (const float*)d_in[2];
    const float* attn_b      = (const float*)d_in[3];
    const float* pw_w        = (const float*)d_in[4];
    const float* pw_b        = (const float*)d_in[5];
    float* out               = (float*)d_out;

    static int smem_set = 0;
    if (!smem_set) {
        cudaFuncSetAttribute(fused_kernel,
                             cudaFuncAttributeMaxDynamicSharedMemorySize,
                             SMEM_FLOATS * 4);
        smem_set = 1;
    }

    pool_kernel<<<B_ * C_, 256>>>(x);
    attn_kernel<<<B_, 128>>>(kernel_bank, attn_w, attn_b);
    split_pw_frag<<<16, 256>>>(pw_w);
    fused_kernel<<<dim3(W_ / 128, H_ / 2, B_), 512, SMEM_FLOATS * 4>>>(x, pw_b, out);
}